// round 1
// baseline (speedup 1.0000x reference)
#include <cuda_runtime.h>

// ---------------- geometry ----------------
#define CIN   64
#define COUT  64
#define DD    16
#define HH    64
#define WW    64
#define POS   (DD*HH*WW)        // 65536
// padded k/v: [COUT][DP][HPD][WPD], interior at (+1,+1,+1)
#define DP    18
#define HPD   66
#define WPD   68
#define HS    (HPD*WPD)         // 4488
#define CS    (DP*HS)           // 80784

// Scratch: zero-initialized device globals. Pad rims of g_K/g_V are NEVER
// written, so they remain zero across all launches (deterministic).
__device__ __align__(16) float g_Q[COUT * POS];
__device__ __align__(16) float g_K[COUT * CS];
__device__ __align__(16) float g_V[COUT * CS];

// ---------------- kernel 1: fused q/k/v projection ----------------
// Grid: (H=64, D=16). Each block computes all 192 output channels (q,k,v
// stacked) for one (d,h) row of 64 w positions.
// Thread layout: 256 = 16 w-quads x 16 co-groups(12 each).
__global__ __launch_bounds__(256) void proj_kernel(
    const float* __restrict__ x,
    const float* __restrict__ wq,
    const float* __restrict__ wk,
    const float* __restrict__ wv)
{
    __shared__ float Wsh[192 * 64];   // 48KB: [co(192)][ci(64)], straight copy
    const int t = threadIdx.x;
    #pragma unroll
    for (int i = 0; i < 16; i++) {
        int idx = t + i * 256;        // 0..4095
        Wsh[idx]        = wq[idx];
        Wsh[idx + 4096] = wk[idx];
        Wsh[idx + 8192] = wv[idx];
    }
    __syncthreads();

    const int h = blockIdx.x;
    const int d = blockIdx.y;
    const int pos0 = d * (HH * WW) + h * WW;

    const int tx  = t & 15;
    const int ty  = t >> 4;
    const int w0  = tx * 4;
    const int co0 = ty * 12;

    float acc[12][4];
    #pragma unroll
    for (int j = 0; j < 12; j++)
        #pragma unroll
        for (int i = 0; i < 4; i++) acc[j][i] = 0.f;

    for (int ci = 0; ci < CIN; ci += 4) {
        float xr[4][4];
        #pragma unroll
        for (int u = 0; u < 4; u++) {
            float4 xv = *(const float4*)(x + (size_t)(ci + u) * POS + pos0 + w0);
            xr[u][0] = xv.x; xr[u][1] = xv.y; xr[u][2] = xv.z; xr[u][3] = xv.w;
        }
        #pragma unroll
        for (int j = 0; j < 12; j++) {
            float4 wv4 = *(const float4*)(Wsh + (co0 + j) * 64 + ci);
            float wr[4] = {wv4.x, wv4.y, wv4.z, wv4.w};
            #pragma unroll
            for (int u = 0; u < 4; u++)
                #pragma unroll
                for (int i = 0; i < 4; i++)
                    acc[j][i] = fmaf(wr[u], xr[u][i], acc[j][i]);
        }
    }

    // scatter: co<64 -> Q (dense), 64..127 -> K (padded), 128..191 -> V (padded)
    #pragma unroll
    for (int j = 0; j < 12; j++) {
        int co = co0 + j;
        if (co < 64) {
            float4 o = {acc[j][0], acc[j][1], acc[j][2], acc[j][3]};
            *(float4*)(g_Q + (size_t)co * POS + pos0 + w0) = o;
        } else if (co < 128) {
            size_t b = (size_t)(co - 64) * CS + (size_t)(d + 1) * HS
                     + (size_t)(h + 1) * WPD + (w0 + 1);
            g_K[b + 0] = acc[j][0]; g_K[b + 1] = acc[j][1];
            g_K[b + 2] = acc[j][2]; g_K[b + 3] = acc[j][3];
        } else {
            size_t b = (size_t)(co - 128) * CS + (size_t)(d + 1) * HS
                     + (size_t)(h + 1) * WPD + (w0 + 1);
            g_V[b + 0] = acc[j][0]; g_V[b + 1] = acc[j][1];
            g_V[b + 2] = acc[j][2]; g_V[b + 3] = acc[j][3];
        }
    }
}

// ---------------- kernel 2: windowed softmax-attention ----------------
// Grid: (h-tiles=8, d=16, c=64); block 128 = 8 h x 16 w-quads.
// Each thread produces 4 outputs along w. Padded taps naturally give
// score q*rel (k=0 in rim) with v=0, matching the reference.
__global__ __launch_bounds__(128) void attn_kernel(
    const float* __restrict__ rel_d,
    const float* __restrict__ rel_h,
    const float* __restrict__ rel_w,
    float* __restrict__ out)
{
    __shared__ float srel[27];
    const int c  = blockIdx.z;
    const int d  = blockIdx.y;
    const int h0 = blockIdx.x * 8;
    const int t  = threadIdx.x;

    if (t < 27) {
        int kd = t / 9, kh = (t / 3) % 3, kw = t % 3;
        float r;
        if (c < 21)      r = rel_d[c * 3 + kd];
        else if (c < 42) r = rel_h[(c - 21) * 3 + kh];
        else             r = rel_w[(c - 42) * 3 + kw];
        srel[t] = r;
    }
    __syncthreads();

    const int ty = t >> 4;
    const int w0 = (t & 15) * 4;
    const int h  = h0 + ty;

    const float LOG2E = 1.4426950408889634f;
    float4 q4 = *(const float4*)(g_Q + (size_t)c * POS + d * (HH * WW) + h * WW + w0);
    float qs[4] = {q4.x * LOG2E, q4.y * LOG2E, q4.z * LOG2E, q4.w * LOG2E};

    float l[4]   = {0.f, 0.f, 0.f, 0.f};
    float acc[4] = {0.f, 0.f, 0.f, 0.f};

    const float* kc = g_K + (size_t)c * CS + (size_t)d * HS + (size_t)h * WPD + w0;
    const float* vc = g_V + (size_t)c * CS + (size_t)d * HS + (size_t)h * WPD + w0;

    #pragma unroll
    for (int kd = 0; kd < 3; kd++) {
        #pragma unroll
        for (int kh = 0; kh < 3; kh++) {
            const float* kp = kc + kd * HS + kh * WPD;   // dp=d+kd, hp=h+kh
            const float* vp = vc + kd * HS + kh * WPD;
            // window [w0-1 .. w0+6] lives at padded wp [w0 .. w0+7]
            float4 ka = ((const float4*)kp)[0];
            float4 kb = ((const float4*)kp)[1];
            float4 va = ((const float4*)vp)[0];
            float4 vb = ((const float4*)vp)[1];
            float kk[8] = {ka.x, ka.y, ka.z, ka.w, kb.x, kb.y, kb.z, kb.w};
            float vv[8] = {va.x, va.y, va.z, va.w, vb.x, vb.y, vb.z, vb.w};
            #pragma unroll
            for (int kw = 0; kw < 3; kw++) {
                float r = srel[(kd * 3 + kh) * 3 + kw];
                #pragma unroll
                for (int i = 0; i < 4; i++) {
                    float s = (kk[i + kw] + r) * qs[i];   // log2-domain score
                    float e;
                    asm("ex2.approx.ftz.f32 %0, %1;" : "=f"(e) : "f"(s));
                    l[i] += e;
                    acc[i] = fmaf(e, vv[i + kw], acc[i]);
                }
            }
        }
    }

    float4 o;
    o.x = __fdividef(acc[0], l[0]);
    o.y = __fdividef(acc[1], l[1]);
    o.z = __fdividef(acc[2], l[2]);
    o.w = __fdividef(acc[3], l[3]);
    *(float4*)(out + (size_t)c * POS + d * (HH * WW) + h * WW + w0) = o;
}

// ---------------- launch ----------------
extern "C" void kernel_launch(void* const* d_in, const int* in_sizes, int n_in,
                              void* d_out, int out_size)
{
    const float* x  = (const float*)d_in[0];
    const float* wq = (const float*)d_in[1];
    const float* wk = (const float*)d_in[2];
    const float* wv = (const float*)d_in[3];
    const float* rd = (const float*)d_in[4];
    const float* rh = (const float*)d_in[5];
    const float* rw = (const float*)d_in[6];
    float* out = (float*)d_out;

    dim3 g1(HH, DD);            // 64 x 16 blocks
    proj_kernel<<<g1, 256>>>(x, wq, wk, wv);

    dim3 g2(HH / 8, DD, COUT);  // 8 x 16 x 64 blocks
    attn_kernel<<<g2, 128>>>(rd, rh, rw, out);
}

// round 2
// speedup vs baseline: 1.1187x; 1.1187x over previous
#include <cuda_runtime.h>

// ---------------- geometry ----------------
#define CIN   64
#define COUT  64
#define DD    16
#define HH    64
#define WW    64
#define POS   (DD*HH*WW)        // 65536
// padded k/v: [COUT][DP][HPD][WPD], interior at (+1,+1,+1)
#define DP    18
#define HPD   66
#define WPD   68
#define HS    (HPD*WPD)         // 4488
#define CS    (DP*HS)           // 80784

typedef unsigned long long u64;

// Scratch: zero-initialized device globals. Pad rims of g_K/g_V are NEVER
// written, so they remain zero across all launches (deterministic).
__device__ __align__(16) float g_Q[COUT * POS];
__device__ __align__(16) float g_K[COUT * CS];
__device__ __align__(16) float g_V[COUT * CS];

// ---------------- f32x2 packed helpers ----------------
__device__ __forceinline__ u64 pk(float lo, float hi) {
    u64 r; asm("mov.b64 %0,{%1,%2};" : "=l"(r) : "f"(lo), "f"(hi)); return r;
}
__device__ __forceinline__ void upk(float& lo, float& hi, u64 v) {
    asm("mov.b64 {%0,%1},%2;" : "=f"(lo), "=f"(hi) : "l"(v));
}
__device__ __forceinline__ u64 fma2(u64 a, u64 b, u64 c) {
    u64 d; asm("fma.rn.f32x2 %0,%1,%2,%3;" : "=l"(d) : "l"(a), "l"(b), "l"(c)); return d;
}
__device__ __forceinline__ u64 add2(u64 a, u64 b) {
    u64 d; asm("add.rn.f32x2 %0,%1,%2;" : "=l"(d) : "l"(a), "l"(b)); return d;
}
__device__ __forceinline__ u64 mul2(u64 a, u64 b) {
    u64 d; asm("mul.rn.f32x2 %0,%1,%2;" : "=l"(d) : "l"(a), "l"(b)); return d;
}
__device__ __forceinline__ float ex2f(float s) {
    float e; asm("ex2.approx.ftz.f32 %0, %1;" : "=f"(e) : "f"(s)); return e;
}

// ---------------- kernel 1: fused q/k/v projection (FFMA2) ----------------
// Grid: (H=64, D=16). Block 256 = 16 w-quads x 16 co-groups(12 each).
// Accumulators are f32x2 pairs over adjacent w positions; x pairs come free
// from float4 loads, weights are (w,w)-broadcast packs on the alu pipe.
__global__ __launch_bounds__(256) void proj_kernel(
    const float* __restrict__ x,
    const float* __restrict__ wq,
    const float* __restrict__ wk,
    const float* __restrict__ wv)
{
    __shared__ float Wsh[192 * 64];   // 48KB: [co(192)][ci(64)]
    const int t = threadIdx.x;
    #pragma unroll
    for (int i = 0; i < 16; i++) {
        int idx = t + i * 256;        // 0..4095
        Wsh[idx]        = wq[idx];
        Wsh[idx + 4096] = wk[idx];
        Wsh[idx + 8192] = wv[idx];
    }
    __syncthreads();

    const int h = blockIdx.x;
    const int d = blockIdx.y;
    const int pos0 = d * (HH * WW) + h * WW;

    const int tx  = t & 15;
    const int ty  = t >> 4;
    const int w0  = tx * 4;
    const int co0 = ty * 12;

    u64 accp[12][2];
    #pragma unroll
    for (int j = 0; j < 12; j++) { accp[j][0] = 0ull; accp[j][1] = 0ull; }

    for (int ci = 0; ci < CIN; ci += 4) {
        u64 xu[4][2];
        #pragma unroll
        for (int u = 0; u < 4; u++) {
            ulonglong2 xv = *(const ulonglong2*)(x + (size_t)(ci + u) * POS + pos0 + w0);
            xu[u][0] = xv.x; xu[u][1] = xv.y;
        }
        #pragma unroll
        for (int j = 0; j < 12; j++) {
            float4 wv4 = *(const float4*)(Wsh + (co0 + j) * 64 + ci);
            float wr[4] = {wv4.x, wv4.y, wv4.z, wv4.w};
            #pragma unroll
            for (int u = 0; u < 4; u++) {
                u64 wp = pk(wr[u], wr[u]);
                accp[j][0] = fma2(wp, xu[u][0], accp[j][0]);
                accp[j][1] = fma2(wp, xu[u][1], accp[j][1]);
            }
        }
    }

    // scatter: co<64 -> Q (dense), 64..127 -> K (padded), 128..191 -> V (padded)
    #pragma unroll
    for (int j = 0; j < 12; j++) {
        int co = co0 + j;
        float a0, a1, a2, a3;
        upk(a0, a1, accp[j][0]);
        upk(a2, a3, accp[j][1]);
        if (co < 64) {
            float4 o = {a0, a1, a2, a3};
            *(float4*)(g_Q + (size_t)co * POS + pos0 + w0) = o;
        } else if (co < 128) {
            size_t b = (size_t)(co - 64) * CS + (size_t)(d + 1) * HS
                     + (size_t)(h + 1) * WPD + (w0 + 1);
            g_K[b + 0] = a0; g_K[b + 1] = a1; g_K[b + 2] = a2; g_K[b + 3] = a3;
        } else {
            size_t b = (size_t)(co - 128) * CS + (size_t)(d + 1) * HS
                     + (size_t)(h + 1) * WPD + (w0 + 1);
            g_V[b + 0] = a0; g_V[b + 1] = a1; g_V[b + 2] = a2; g_V[b + 3] = a3;
        }
    }
}

// ---------------- kernel 2: windowed softmax-attention (packed) ----------------
// Grid: (h-tiles=8, d=16, c=64); block 128 = 8 h x 16 w-quads.
// Each thread produces 4 outputs along w as two f32x2 pairs. ex2 stays
// scalar (MUFU); everything else rides packed fma-pipe ops.
__global__ __launch_bounds__(128) void attn_kernel(
    const float* __restrict__ rel_d,
    const float* __restrict__ rel_h,
    const float* __restrict__ rel_w,
    float* __restrict__ out)
{
    __shared__ u64 srel2[27];
    const int c  = blockIdx.z;
    const int d  = blockIdx.y;
    const int h0 = blockIdx.x * 8;
    const int t  = threadIdx.x;

    if (t < 27) {
        int kd = t / 9, kh = (t / 3) % 3, kw = t % 3;
        float r;
        if (c < 21)      r = rel_d[c * 3 + kd];
        else if (c < 42) r = rel_h[(c - 21) * 3 + kh];
        else             r = rel_w[(c - 42) * 3 + kw];
        srel2[t] = pk(r, r);
    }
    __syncthreads();

    const int ty = t >> 4;
    const int w0 = (t & 15) * 4;
    const int h  = h0 + ty;

    const float LOG2E = 1.4426950408889634f;
    float4 q4 = *(const float4*)(g_Q + (size_t)c * POS + d * (HH * WW) + h * WW + w0);
    u64 qp[2] = { pk(q4.x * LOG2E, q4.y * LOG2E), pk(q4.z * LOG2E, q4.w * LOG2E) };

    u64 lp[2]   = {0ull, 0ull};
    u64 accp[2] = {0ull, 0ull};

    const float* kc = g_K + (size_t)c * CS + (size_t)d * HS + (size_t)h * WPD + w0;
    const float* vc = g_V + (size_t)c * CS + (size_t)d * HS + (size_t)h * WPD + w0;

    #pragma unroll
    for (int kd = 0; kd < 3; kd++) {
        #pragma unroll
        for (int kh = 0; kh < 3; kh++) {
            const float* kp = kc + kd * HS + kh * WPD;   // padded (d+kd, h+kh)
            const float* vp = vc + kd * HS + kh * WPD;
            // window offsets [0..5] cover outputs w0..w0+3, taps kw=0..2
            ulonglong2 ka = *(const ulonglong2*)kp;       // (k0,k1),(k2,k3)
            u64 ku2 = *(const u64*)(kp + 4);              // (k4,k5)
            ulonglong2 va = *(const ulonglong2*)vp;
            u64 vu2 = *(const u64*)(vp + 4);

            float k0_, k1_, k2_, k3_, k4_, k5_;
            upk(k0_, k1_, ka.x); upk(k2_, k3_, ka.y); upk(k4_, k5_, ku2);
            float v0_, v1_, v2_, v3_, v4_, v5_;
            upk(v0_, v1_, va.x); upk(v2_, v3_, va.y); upk(v4_, v5_, vu2);

            // per-kw packed pairs: pair0 -> (kw, kw+1), pair1 -> (kw+2, kw+3)
            u64 kpr[3][2] = { {ka.x, ka.y},
                              {pk(k1_, k2_), pk(k3_, k4_)},
                              {ka.y, ku2} };
            u64 vpr[3][2] = { {va.x, va.y},
                              {pk(v1_, v2_), pk(v3_, v4_)},
                              {va.y, vu2} };

            #pragma unroll
            for (int kw = 0; kw < 3; kw++) {
                u64 rr = srel2[(kd * 3 + kh) * 3 + kw];
                #pragma unroll
                for (int p = 0; p < 2; p++) {
                    u64 s = mul2(add2(kpr[kw][p], rr), qp[p]);  // log2-domain
                    float s0, s1; upk(s0, s1, s);
                    u64 e = pk(ex2f(s0), ex2f(s1));
                    lp[p]   = add2(lp[p], e);
                    accp[p] = fma2(e, vpr[kw][p], accp[p]);
                }
            }
        }
    }

    float l0, l1, l2, l3, a0, a1, a2, a3;
    upk(l0, l1, lp[0]); upk(l2, l3, lp[1]);
    upk(a0, a1, accp[0]); upk(a2, a3, accp[1]);
    float4 o;
    o.x = __fdividef(a0, l0);
    o.y = __fdividef(a1, l1);
    o.z = __fdividef(a2, l2);
    o.w = __fdividef(a3, l3);
    *(float4*)(out + (size_t)c * POS + d * (HH * WW) + h * WW + w0) = o;
}

// ---------------- launch ----------------
extern "C" void kernel_launch(void* const* d_in, const int* in_sizes, int n_in,
                              void* d_out, int out_size)
{
    const float* x  = (const float*)d_in[0];
    const float* wq = (const float*)d_in[1];
    const float* wk = (const float*)d_in[2];
    const float* wv = (const float*)d_in[3];
    const float* rd = (const float*)d_in[4];
    const float* rh = (const float*)d_in[5];
    const float* rw = (const float*)d_in[6];
    float* out = (float*)d_out;

    dim3 g1(HH, DD);            // 64 x 16 blocks
    proj_kernel<<<g1, 256>>>(x, wq, wk, wv);

    dim3 g2(HH / 8, DD, COUT);  // 8 x 16 x 64 blocks
    attn_kernel<<<g2, 128>>>(rd, rh, rw, out);
}

// round 3
// speedup vs baseline: 1.1692x; 1.0451x over previous
#include <cuda_runtime.h>

// ---------------- geometry ----------------
#define CIN   64
#define COUT  64
#define DD    16
#define HH    64
#define WW    64
#define POS   (DD*HH*WW)        // 65536
// padded k/v: [COUT][DP][HPD][WPD], interior at (+1,+1,+1)
#define DP    18
#define HPD   66
#define WPD   68
#define HS    (HPD*WPD)         // 4488
#define CS    (DP*HS)           // 80784

typedef unsigned long long u64;

// Scratch: zero-initialized device globals. Pad rims of g_K/g_V are NEVER
// written, so they remain zero across all launches (deterministic).
__device__ __align__(16) float g_Q[COUT * POS];
__device__ __align__(16) float g_K[COUT * CS];
__device__ __align__(16) float g_V[COUT * CS];

// ---------------- f32x2 packed helpers ----------------
__device__ __forceinline__ u64 pk(float lo, float hi) {
    u64 r; asm("mov.b64 %0,{%1,%2};" : "=l"(r) : "f"(lo), "f"(hi)); return r;
}
__device__ __forceinline__ void upk(float& lo, float& hi, u64 v) {
    asm("mov.b64 {%0,%1},%2;" : "=f"(lo), "=f"(hi) : "l"(v));
}
__device__ __forceinline__ u64 fma2(u64 a, u64 b, u64 c) {
    u64 d; asm("fma.rn.f32x2 %0,%1,%2,%3;" : "=l"(d) : "l"(a), "l"(b), "l"(c)); return d;
}
__device__ __forceinline__ float ex2f(float s) {
    float e; asm("ex2.approx.ftz.f32 %0, %1;" : "=f"(e) : "f"(s)); return e;
}

// ---------------- kernel 1: fused q/k/v projection (FFMA2, x-broadcast) ----
// Grid: (H=64, D=16). Block 256 = 16 w-quads x 16 co-groups (12 co each).
// Accumulators pack ADJACENT OUTPUT CHANNELS (co, co+1) per w position; the
// co-pair weights load as one LDS.64 from a transposed [ci][co] shared tile
// (warp-broadcast), and only x needs (x,x) packs: 4 per ci vs 12 per ci
// for the w-packed variant. x loads are software-prefetched one batch ahead.
#define WT_STRIDE 198   // floats; even (u64 align), 198%32=6 -> ~2-way write conflict only
__global__ __launch_bounds__(256) void proj_kernel(
    const float* __restrict__ x,
    const float* __restrict__ wq,
    const float* __restrict__ wk,
    const float* __restrict__ wv)
{
    __shared__ float Wt[64 * WT_STRIDE];   // ~50.7KB, [ci][co0..191]
    const int t = threadIdx.x;
    #pragma unroll
    for (int i = 0; i < 16; i++) {
        int idx = t + i * 256;             // 0..4095
        int co = idx >> 6, ci = idx & 63;
        Wt[ci * WT_STRIDE + co]       = wq[idx];
        Wt[ci * WT_STRIDE + 64 + co]  = wk[idx];
        Wt[ci * WT_STRIDE + 128 + co] = wv[idx];
    }
    __syncthreads();

    const int h = blockIdx.x;
    const int d = blockIdx.y;
    const int pos0 = d * (HH * WW) + h * WW;

    const int tx  = t & 15;
    const int ty  = t >> 4;
    const int w0  = tx * 4;
    const int co0 = ty * 12;               // 12 co = 6 co-pairs

    u64 acc[6][4];                          // [co-pair][w]
    #pragma unroll
    for (int jp = 0; jp < 6; jp++)
        #pragma unroll
        for (int i = 0; i < 4; i++) acc[jp][i] = 0ull;

    const float* xb = x + pos0 + w0;
    float4 xf0 = *(const float4*)(xb + 0 * POS);
    float4 xf1 = *(const float4*)(xb + 1 * POS);
    float4 xf2 = *(const float4*)(xb + 2 * POS);
    float4 xf3 = *(const float4*)(xb + 3 * POS);

    for (int cib = 0; cib < 64; cib += 4) {
        // prefetch next batch (wraps to batch 0 on last iter; harmless L2 hit)
        int cin = (cib + 4) & 63;
        float4 xn0 = *(const float4*)(xb + (size_t)(cin + 0) * POS);
        float4 xn1 = *(const float4*)(xb + (size_t)(cin + 1) * POS);
        float4 xn2 = *(const float4*)(xb + (size_t)(cin + 2) * POS);
        float4 xn3 = *(const float4*)(xb + (size_t)(cin + 3) * POS);

        float4 xc[4] = {xf0, xf1, xf2, xf3};
        #pragma unroll
        for (int u = 0; u < 4; u++) {
            int ci = cib + u;
            u64 xp[4] = { pk(xc[u].x, xc[u].x), pk(xc[u].y, xc[u].y),
                          pk(xc[u].z, xc[u].z), pk(xc[u].w, xc[u].w) };
            const u64* Wrow = (const u64*)(Wt + ci * WT_STRIDE + co0);
            #pragma unroll
            for (int jp = 0; jp < 6; jp++) {
                u64 wp = Wrow[jp];          // (w[co0+2jp], w[co0+2jp+1]) broadcast
                #pragma unroll
                for (int i = 0; i < 4; i++)
                    acc[jp][i] = fma2(wp, xp[i], acc[jp][i]);
            }
        }
        xf0 = xn0; xf1 = xn1; xf2 = xn2; xf3 = xn3;
    }

    // scatter: co<64 -> Q (dense), 64..127 -> K (padded), 128..191 -> V (padded)
    #pragma unroll
    for (int jp = 0; jp < 6; jp++) {
        float lo[4], hi[4];
        #pragma unroll
        for (int i = 0; i < 4; i++) upk(lo[i], hi[i], acc[jp][i]);
        #pragma unroll
        for (int half = 0; half < 2; half++) {
            int co = co0 + 2 * jp + half;
            const float* f = half ? hi : lo;
            if (co < 64) {
                float4 o = {f[0], f[1], f[2], f[3]};
                *(float4*)(g_Q + (size_t)co * POS + pos0 + w0) = o;
            } else if (co < 128) {
                size_t b = (size_t)(co - 64) * CS + (size_t)(d + 1) * HS
                         + (size_t)(h + 1) * WPD + (w0 + 1);
                g_K[b + 0] = f[0]; g_K[b + 1] = f[1];
                g_K[b + 2] = f[2]; g_K[b + 3] = f[3];
            } else {
                size_t b = (size_t)(co - 128) * CS + (size_t)(d + 1) * HS
                         + (size_t)(h + 1) * WPD + (w0 + 1);
                g_V[b + 0] = f[0]; g_V[b + 1] = f[1];
                g_V[b + 2] = f[2]; g_V[b + 3] = f[3];
            }
        }
    }
}

// ---------------- kernel 2: windowed softmax-attention (scalar, round-1) ----
// Grid: (h-tiles=8, d=16, c=64); block 128 = 8 h x 16 w-quads.
// Each thread produces 4 outputs along w. Padded taps naturally give
// score q*rel (k=0 in rim) with v=0, matching the reference.
// Row loads trimmed to the 6 needed floats: float4 + float2.
__global__ __launch_bounds__(128) void attn_kernel(
    const float* __restrict__ rel_d,
    const float* __restrict__ rel_h,
    const float* __restrict__ rel_w,
    float* __restrict__ out)
{
    __shared__ float srel[27];
    const int c  = blockIdx.z;
    const int d  = blockIdx.y;
    const int h0 = blockIdx.x * 8;
    const int t  = threadIdx.x;

    if (t < 27) {
        int kd = t / 9, kh = (t / 3) % 3, kw = t % 3;
        float r;
        if (c < 21)      r = rel_d[c * 3 + kd];
        else if (c < 42) r = rel_h[(c - 21) * 3 + kh];
        else             r = rel_w[(c - 42) * 3 + kw];
        srel[t] = r;
    }
    __syncthreads();

    const int ty = t >> 4;
    const int w0 = (t & 15) * 4;
    const int h  = h0 + ty;

    const float LOG2E = 1.4426950408889634f;
    float4 q4 = *(const float4*)(g_Q + (size_t)c * POS + d * (HH * WW) + h * WW + w0);
    float qs[4] = {q4.x * LOG2E, q4.y * LOG2E, q4.z * LOG2E, q4.w * LOG2E};

    float l[4]   = {0.f, 0.f, 0.f, 0.f};
    float acc[4] = {0.f, 0.f, 0.f, 0.f};

    const float* kc = g_K + (size_t)c * CS + (size_t)d * HS + (size_t)h * WPD + w0;
    const float* vc = g_V + (size_t)c * CS + (size_t)d * HS + (size_t)h * WPD + w0;

    #pragma unroll
    for (int kd = 0; kd < 3; kd++) {
        #pragma unroll
        for (int kh = 0; kh < 3; kh++) {
            const float* kp = kc + kd * HS + kh * WPD;   // padded (d+kd, h+kh)
            const float* vp = vc + kd * HS + kh * WPD;
            // window [w0-1 .. w0+6] lives at padded wp [w0 .. w0+5] (6 floats)
            float4 ka = *(const float4*)kp;
            float2 kb = *(const float2*)(kp + 4);
            float4 va = *(const float4*)vp;
            float2 vb = *(const float2*)(vp + 4);
            float kk[6] = {ka.x, ka.y, ka.z, ka.w, kb.x, kb.y};
            float vv[6] = {va.x, va.y, va.z, va.w, vb.x, vb.y};
            #pragma unroll
            for (int kw = 0; kw < 3; kw++) {
                float r = srel[(kd * 3 + kh) * 3 + kw];
                #pragma unroll
                for (int i = 0; i < 4; i++) {
                    float s = (kk[i + kw] + r) * qs[i];   // log2-domain score
                    float e = ex2f(s);
                    l[i] += e;
                    acc[i] = fmaf(e, vv[i + kw], acc[i]);
                }
            }
        }
    }

    float4 o;
    o.x = __fdividef(acc[0], l[0]);
    o.y = __fdividef(acc[1], l[1]);
    o.z = __fdividef(acc[2], l[2]);
    o.w = __fdividef(acc[3], l[3]);
    *(float4*)(out + (size_t)c * POS + d * (HH * WW) + h * WW + w0) = o;
}

// ---------------- launch ----------------
extern "C" void kernel_launch(void* const* d_in, const int* in_sizes, int n_in,
                              void* d_out, int out_size)
{
    const float* x  = (const float*)d_in[0];
    const float* wq = (const float*)d_in[1];
    const float* wk = (const float*)d_in[2];
    const float* wv = (const float*)d_in[3];
    const float* rd = (const float*)d_in[4];
    const float* rh = (const float*)d_in[5];
    const float* rw = (const float*)d_in[6];
    float* out = (float*)d_out;

    dim3 g1(HH, DD);            // 64 x 16 blocks
    proj_kernel<<<g1, 256>>>(x, wq, wk, wv);

    dim3 g2(HH / 8, DD, COUT);  // 8 x 16 x 64 blocks
    attn_kernel<<<g2, 128>>>(rd, rh, rw, out);
}

// round 8
// speedup vs baseline: 1.4544x; 1.2439x over previous
#include <cuda_runtime.h>
#include <cuda_bf16.h>
#include <cstdint>

// ---------------- geometry ----------------
#define CIN   64
#define COUT  64
#define DD    16
#define HH    64
#define WW    64
#define POS   (DD*HH*WW)        // 65536
// padded k/v: [COUT][DP][HPD][WPD], interior at (+1,+1,+1)
#define DP    18
#define HPD   66
#define WPD   68
#define HS    (HPD*WPD)         // 4488
#define CS    (DP*HS)           // 80784

// Scratch: zero-initialized device globals. Pad rims of g_K/g_V are NEVER
// written, so they remain zero across all launches (deterministic).
__device__ __align__(16) float g_Q[COUT * POS];
__device__ __align__(16) float g_K[COUT * CS];
__device__ __align__(16) float g_V[COUT * CS];
// W in bf16 hi/lo split, [192 co][64 ci] (q:0-63, k:64-127, v:128-191)
__device__ __align__(16) unsigned short g_WH[192 * 64];
__device__ __align__(16) unsigned short g_WL[192 * 64];

__device__ __forceinline__ float ex2f(float s) {
    float e; asm("ex2.approx.ftz.f32 %0, %1;" : "=f"(e) : "f"(s)); return e;
}
__device__ __forceinline__ void mma16816(float* d, const unsigned* a,
                                         unsigned b0, unsigned b1) {
    asm volatile(
        "mma.sync.aligned.m16n8k16.row.col.f32.bf16.bf16.f32 "
        "{%0,%1,%2,%3},{%4,%5,%6,%7},{%8,%9},{%0,%1,%2,%3};"
        : "+f"(d[0]), "+f"(d[1]), "+f"(d[2]), "+f"(d[3])
        : "r"(a[0]), "r"(a[1]), "r"(a[2]), "r"(a[3]), "r"(b0), "r"(b1));
}
__device__ __forceinline__ unsigned bf16_hi(float v) {
    return (unsigned)__bfloat16_as_ushort(__float2bfloat16(v));
}

// ---------------- kernel 0: W -> bf16 hi/lo split ----------------
__global__ void wprep_kernel(const float* __restrict__ wq,
                             const float* __restrict__ wk,
                             const float* __restrict__ wv)
{
    int e = blockIdx.x * 1024 + threadIdx.x;      // 0..12287
    float v = (e < 4096) ? wq[e] : (e < 8192) ? wk[e - 4096] : wv[e - 8192];
    unsigned hu = bf16_hi(v);
    float hif = __uint_as_float(hu << 16);
    g_WH[e] = (unsigned short)hu;
    g_WL[e] = (unsigned short)bf16_hi(v - hif);
}

// ---------------- kernel 1: projection via mma.sync bf16 triple-split ----
// C[192 co][128 pos tile] = W[192x64] @ X[64x128], fp32 accum,
// products Whi*Xhi + Whi*Xlo + Wlo*Xhi.
// Block 256 = 8 warps: warp w -> co-group (w>>1)*48, pos-half (w&1)*64.
// B tiles: n-major bf16 rows, 144B stride (conflict-free fragment LDS).
#define STG_STRIDE 132                      // fp32 words per stage row
#define B_STRIDE   144                      // bytes per B row (64 bf16 + pad)
#define SM_STAGE_BYTES (64 * STG_STRIDE * 4)    // 33792
#define SM_BHI  SM_STAGE_BYTES
#define SM_BLO  (SM_BHI + 128 * B_STRIDE)       // +18432
#define SMEM_DYN (SM_BLO + 128 * B_STRIDE)      // 70656

__global__ __launch_bounds__(256) void proj_mma_kernel(const float* __restrict__ x)
{
    extern __shared__ __align__(16) char sm[];
    float* stage = (float*)sm;
    char*  Bhi   = sm + SM_BHI;
    char*  Blo   = sm + SM_BLO;

    const int t    = threadIdx.x;
    const int wid  = t >> 5;
    const int lane = t & 31;
    const int pos0 = blockIdx.x * 128;

    // ---- load x tile [64 ci][128 pos] into fp32 stage (coalesced) ----
    #pragma unroll
    for (int i = 0; i < 8; i++) {
        int idx4 = i * 256 + t;             // 0..2047 float4s
        int ci = idx4 >> 5, pq = idx4 & 31;
        float4 vx = *(const float4*)(x + (size_t)ci * POS + pos0 + pq * 4);
        *(float4*)(stage + ci * STG_STRIDE + pq * 4) = vx;
    }
    __syncthreads();

    // ---- transpose + bf16 hi/lo: build B tiles [pos][ci] ----
    {
        const int p = t & 127;
        const int halfsel = t >> 7;         // ci half 0/1
        #pragma unroll
        for (int oc = 0; oc < 4; oc++) {
            int ci0 = halfsel * 32 + oc * 8;
            unsigned hb[8], lb[8];
            #pragma unroll
            for (int j = 0; j < 8; j++) {
                float v = stage[(ci0 + j) * STG_STRIDE + p];
                unsigned hu = bf16_hi(v);
                hb[j] = hu;
                lb[j] = bf16_hi(v - __uint_as_float(hu << 16));
            }
            uint4 H = { hb[0] | (hb[1] << 16), hb[2] | (hb[3] << 16),
                        hb[4] | (hb[5] << 16), hb[6] | (hb[7] << 16) };
            uint4 L = { lb[0] | (lb[1] << 16), lb[2] | (lb[3] << 16),
                        lb[4] | (lb[5] << 16), lb[6] | (lb[7] << 16) };
            *(uint4*)(Bhi + p * B_STRIDE + ci0 * 2) = H;
            *(uint4*)(Blo + p * B_STRIDE + ci0 * 2) = L;
        }
    }
    __syncthreads();

    // ---- MMA: warp tile 48 co x 64 pos, K=64 in 4 steps, 3 products ----
    const int cg  = wid >> 1;
    const int ph  = wid & 1;
    const int co0 = cg * 48;
    const int nb  = ph * 64;
    const int r   = lane >> 2;
    const int qd  = lane & 3;

    float d[3][8][4];
    #pragma unroll
    for (int m = 0; m < 3; m++)
        #pragma unroll
        for (int n = 0; n < 8; n++)
            #pragma unroll
            for (int i = 0; i < 4; i++) d[m][n][i] = 0.f;

    const char* WHb = (const char*)g_WH;
    const char* WLb = (const char*)g_WL;

    #pragma unroll
    for (int k = 0; k < 4; k++) {
        unsigned AH[3][4], AL[3][4];
        #pragma unroll
        for (int m = 0; m < 3; m++) {
            int byte0 = (co0 + m * 16 + r) * 128 + k * 32 + qd * 4;
            AH[m][0] = *(const unsigned*)(WHb + byte0);
            AH[m][1] = *(const unsigned*)(WHb + byte0 + 8 * 128);
            AH[m][2] = *(const unsigned*)(WHb + byte0 + 16);
            AH[m][3] = *(const unsigned*)(WHb + byte0 + 8 * 128 + 16);
            AL[m][0] = *(const unsigned*)(WLb + byte0);
            AL[m][1] = *(const unsigned*)(WLb + byte0 + 8 * 128);
            AL[m][2] = *(const unsigned*)(WLb + byte0 + 16);
            AL[m][3] = *(const unsigned*)(WLb + byte0 + 8 * 128 + 16);
        }
        #pragma unroll
        for (int n = 0; n < 8; n++) {
            int boff = (nb + n * 8 + r) * B_STRIDE + k * 32 + qd * 4;
            unsigned bh0 = *(const unsigned*)(Bhi + boff);
            unsigned bh1 = *(const unsigned*)(Bhi + boff + 16);
            unsigned bl0 = *(const unsigned*)(Blo + boff);
            unsigned bl1 = *(const unsigned*)(Blo + boff + 16);
            #pragma unroll
            for (int m = 0; m < 3; m++) {
                mma16816(d[m][n], AH[m], bh0, bh1);
                mma16816(d[m][n], AH[m], bl0, bl1);
                mma16816(d[m][n], AL[m], bh0, bh1);
            }
        }
    }

    // ---- epilogue: scatter to Q (dense) / K,V (padded) ----
    #pragma unroll
    for (int n = 0; n < 8; n++) {
        int pos = pos0 + nb + n * 8 + qd * 2;
        int dz = pos >> 12, hy = (pos >> 6) & 63, wx = pos & 63;
        size_t kvoff = (size_t)(dz + 1) * HS + (size_t)(hy + 1) * WPD + (wx + 1);
        #pragma unroll
        for (int m = 0; m < 3; m++) {
            #pragma unroll
            for (int half = 0; half < 2; half++) {
                int co = co0 + m * 16 + r + half * 8;
                float x0 = d[m][n][half * 2], x1 = d[m][n][half * 2 + 1];
                if (co < 64) {
                    float2 o = {x0, x1};
                    *(float2*)(g_Q + (size_t)co * POS + pos) = o;
                } else if (co < 128) {
                    float* dst = g_K + (size_t)(co - 64) * CS + kvoff;
                    dst[0] = x0; dst[1] = x1;
                } else {
                    float* dst = g_V + (size_t)(co - 128) * CS + kvoff;
                    dst[0] = x0; dst[1] = x1;
                }
            }
        }
    }
}

// ---------------- kernel 2: windowed softmax-attention (scalar) ----------
// Grid: (h-tiles=8, d=16, c=64); block 128 = 8 h x 16 w-quads.
// Padded taps naturally give score q*rel (k=0 in rim) with v=0.
__global__ __launch_bounds__(128) void attn_kernel(
    const float* __restrict__ rel_d,
    const float* __restrict__ rel_h,
    const float* __restrict__ rel_w,
    float* __restrict__ out)
{
    __shared__ float srel[27];
    const int c  = blockIdx.z;
    const int d  = blockIdx.y;
    const int h0 = blockIdx.x * 8;
    const int t  = threadIdx.x;

    if (t < 27) {
        int kd = t / 9, kh = (t / 3) % 3, kw = t % 3;
        float r;
        if (c < 21)      r = rel_d[c * 3 + kd];
        else if (c < 42) r = rel_h[(c - 21) * 3 + kh];
        else             r = rel_w[(c - 42) * 3 + kw];
        srel[t] = r;
    }
    __syncthreads();

    const int ty = t >> 4;
    const int w0 = (t & 15) * 4;
    const int h  = h0 + ty;

    const float LOG2E = 1.4426950408889634f;
    float4 q4 = *(const float4*)(g_Q + (size_t)c * POS + d * (HH * WW) + h * WW + w0);
    float qs[4] = {q4.x * LOG2E, q4.y * LOG2E, q4.z * LOG2E, q4.w * LOG2E};

    float l[4]   = {0.f, 0.f, 0.f, 0.f};
    float acc[4] = {0.f, 0.f, 0.f, 0.f};

    const float* kc = g_K + (size_t)c * CS + (size_t)d * HS + (size_t)h * WPD + w0;
    const float* vc = g_V + (size_t)c * CS + (size_t)d * HS + (size_t)h * WPD + w0;

    #pragma unroll
    for (int kd = 0; kd < 3; kd++) {
        #pragma unroll
        for (int kh = 0; kh < 3; kh++) {
            const float* kp = kc + kd * HS + kh * WPD;
            const float* vp = vc + kd * HS + kh * WPD;
            float4 ka = *(const float4*)kp;
            float2 kb = *(const float2*)(kp + 4);
            float4 va = *(const float4*)vp;
            float2 vb = *(const float2*)(vp + 4);
            float kk[6] = {ka.x, ka.y, ka.z, ka.w, kb.x, kb.y};
            float vv[6] = {va.x, va.y, va.z, va.w, vb.x, vb.y};
            #pragma unroll
            for (int kw = 0; kw < 3; kw++) {
                float r = srel[(kd * 3 + kh) * 3 + kw];
                #pragma unroll
                for (int i = 0; i < 4; i++) {
                    float s = (kk[i + kw] + r) * qs[i];
                    float e = ex2f(s);
                    l[i] += e;
                    acc[i] = fmaf(e, vv[i + kw], acc[i]);
                }
            }
        }
    }

    float4 o;
    o.x = __fdividef(acc[0], l[0]);
    o.y = __fdividef(acc[1], l[1]);
    o.z = __fdividef(acc[2], l[2]);
    o.w = __fdividef(acc[3], l[3]);
    *(float4*)(out + (size_t)c * POS + d * (HH * WW) + h * WW + w0) = o;
}

// ---------------- launch ----------------
extern "C" void kernel_launch(void* const* d_in, const int* in_sizes, int n_in,
                              void* d_out, int out_size)
{
    const float* x  = (const float*)d_in[0];
    const float* wq = (const float*)d_in[1];
    const float* wk = (const float*)d_in[2];
    const float* wv = (const float*)d_in[3];
    const float* rd = (const float*)d_in[4];
    const float* rh = (const float*)d_in[5];
    const float* rw = (const float*)d_in[6];
    float* out = (float*)d_out;

    cudaFuncSetAttribute(proj_mma_kernel,
                         cudaFuncAttributeMaxDynamicSharedMemorySize, SMEM_DYN);

    wprep_kernel<<<12, 1024>>>(wq, wk, wv);
    proj_mma_kernel<<<POS / 128, 256, SMEM_DYN>>>(x);

    dim3 g2(HH / 8, DD, COUT);
    attn_kernel<<<g2, 128>>>(rd, rh, rw, out);
}